// round 11
// baseline (speedup 1.0000x reference)
#include <cuda_runtime.h>
#include <cstdint>

#define NN 50000
#define DD 128
#define EDIM 16
#define NE 800000
#define NB 49        // ceil(NN/1024)
#define CHUNK 16
#define BATCH 8
#define NCHUNK (NE / CHUNK)   // 50000

#define ACC_BLOCKS 592
#define ACC_WARPS (ACC_BLOCKS * 4)            // 2368
#define GPER ((NCHUNK + ACC_WARPS - 1) / ACC_WARPS)   // 22 chunks -> 352 edges/warp

// dynamic smem layout (per warp, in 4-byte words):
//  nf: 3 bufs * 8 edges * 128 ch = 3072
//  ef: 3 bufs * 8 edges * 16    = 384   (offset 3072)
//  dst: 3 bufs * 8               = 24    (offset 3456)
#define WARP_WORDS 3488
#define ACC_SMEM (4 * WARP_WORDS * 4)         // 55808 bytes

// packed fp32x2 helpers (Blackwell FFMA2 path)
#define PACK2(d, lo, hi)  asm("mov.b64 %0, {%1, %2};" : "=l"(d) : "f"(lo), "f"(hi))
#define UNPACK2(lo, hi, s) asm("mov.b64 {%0, %1}, %2;" : "=f"(lo), "=f"(hi) : "l"(s))
#define FMA2(d, a, b, c)  asm("fma.rn.f32x2 %0, %1, %2, %3;" : "=l"(d) : "l"(a), "l"(b), "l"(c))
#define ADD2(d, a, b)     asm("add.rn.f32x2 %0, %1, %2;" : "=l"(d) : "l"(a), "l"(b))
#define RED4(p, v) asm volatile("red.global.add.v4.f32 [%0], {%1, %2, %3, %4};" \
                                :: "l"(p), "f"((v).x), "f"((v).y), "f"((v).z), "f"((v).w) : "memory")
#define CPASYNC16(sm, gp) asm volatile("cp.async.ca.shared.global [%0], [%1], 16;" \
                                       :: "r"(sm), "l"(gp) : "memory")
#define CPCOMMIT() asm volatile("cp.async.commit_group;" ::: "memory")
#define CPWAIT(n)  asm volatile("cp.async.wait_group %0;" :: "n"(n) : "memory")

// ---------------- device scratch ----------------
__device__ float g_Wef[EDIM * DD];
__device__ float g_bef[DD];
__device__ float g_W1[DD * 256];
__device__ float g_b1[256];
__device__ float g_W2[256 * DD];
__device__ float g_b2[DD];
__device__ float g_acc[(size_t)NN * DD];
__device__ float g_t[(size_t)NN * 256];
__device__ int   g_count[NN];     // zero at entry (static init / re-zeroed by gemm2)
__device__ int   g_cursor[NN];    // zero at entry (same)
__device__ int   g_csum[NN];      // per-tile inclusive scan (no global offset)
__device__ int   g_bsum[64];
__device__ int4  g_epack4[NE];    // sorted by dst: (edge_id, src, dst, 0)

// ---------------- L1: prep (blocks 0..127) + hist (blocks 128..) ----------------
__global__ void prep_hist_kernel(const float* __restrict__ We1, const float* __restrict__ be1,
                                 const float* __restrict__ We2, const float* __restrict__ be2,
                                 const float* __restrict__ Wm1, const float* __restrict__ bm1,
                                 const float* __restrict__ g1, const float* __restrict__ b1,
                                 const float* __restrict__ m1, const float* __restrict__ v1,
                                 const float* __restrict__ Wm2, const float* __restrict__ bm2,
                                 const float* __restrict__ g2, const float* __restrict__ b2,
                                 const float* __restrict__ m2, const float* __restrict__ v2,
                                 const int* __restrict__ dst) {
    if (blockIdx.x >= 128) {
        int e = (blockIdx.x - 128) * 256 + threadIdx.x;
        if (e < NE) atomicAdd(&g_count[dst[e]], 1);
        return;
    }
    int i = blockIdx.x * 256 + threadIdx.x;   // 0..32767

    if (i < EDIM * DD) {
        int k = i / DD, d = i % DD;
        float s = 0.f;
        for (int j = 0; j < 256; j++) s += We1[k * 256 + j] * We2[j * DD + d];
        g_Wef[i] = s;
    }
    if (i < DD) {
        float s = be2[i];
        for (int j = 0; j < 256; j++) s += be1[j] * We2[j * DD + i];
        g_bef[i] = s;
    }
    if (i < DD * 256) {
        int j = i % 256;
        float a = g1[j] * rsqrtf(v1[j] + 1e-3f);
        g_W1[i] = Wm1[i] * a;
    }
    if (i < 256) {
        float a = g1[i] * rsqrtf(v1[i] + 1e-3f);
        g_b1[i] = bm1[i] * a + b1[i] - m1[i] * a;
    }
    if (i < 256 * DD) {
        int j = i % DD;
        float a = g2[j] * rsqrtf(v2[j] + 1e-3f);
        g_W2[i] = Wm2[i] * a;
    }
    if (i < DD) {
        float a = g2[i] * rsqrtf(v2[i] + 1e-3f);
        g_b2[i] = bm2[i] * a + b2[i] - m2[i] * a;
    }
}

// ---------------- L2: per-tile inclusive scan + block sums ----------------
__global__ void scan1_kernel() {
    __shared__ int sm[1024];
    int i = blockIdx.x * 1024 + threadIdx.x;
    int v = (i < NN) ? g_count[i] : 0;
    sm[threadIdx.x] = v;
    __syncthreads();
    for (int off = 1; off < 1024; off <<= 1) {
        int add = (threadIdx.x >= off) ? sm[threadIdx.x - off] : 0;
        __syncthreads();
        sm[threadIdx.x] += add;
        __syncthreads();
    }
    if (i < NN) g_csum[i] = sm[threadIdx.x];
    if (threadIdx.x == 1023) g_bsum[blockIdx.x] = sm[1023];
}

// ---------------- L3: init_acc (blocks 0..6249) + scatter (blocks 6250..) ----------------
#define INIT_BLOCKS 6250   // 1,600,000 float4 / 256
__global__ void scatter_init_kernel(const int* __restrict__ src, const int* __restrict__ dst,
                                    const float4* __restrict__ node4,
                                    const float* __restrict__ eps) {
    if (blockIdx.x < INIT_BLOCKS) {
        int i = blockIdx.x * 256 + threadIdx.x;
        float s = 1.f + eps[0];
        float4 v = node4[i];
        v.x *= s; v.y *= s; v.z *= s; v.w *= s;
        reinterpret_cast<float4*>(g_acc)[i] = v;
        return;
    }
    int i = (blockIdx.x - INIT_BLOCKS) * 256 + threadIdx.x;
    if (i < NE) {
        int t = dst[i];
        int tb = t >> 10;
        int off = 0;
        for (int j = 0; j < tb; j++) off += g_bsum[j];
        int beg = g_csum[t] + off - g_count[t];
        int pos = beg + atomicAdd(&g_cursor[t], 1);
        g_epack4[pos] = make_int4(i, src[i], t, 0);
    }
}

// ---------------- L4: persistent 3-stage cp.async segmented accumulation ----------------
__global__ void __launch_bounds__(128) accum_kernel(const float* __restrict__ node,
                                                    const float* __restrict__ efeat) {
    extern __shared__ float dsm[];
    const int lane = threadIdx.x;
    const int w = threadIdx.y;
    float* wb = dsm + w * WARP_WORDS;
    int* dstb = reinterpret_cast<int*>(wb + 3456);

    uint64_t w2[EDIM][2];
#pragma unroll
    for (int k = 0; k < EDIM; k++) {
        float4 wv = *reinterpret_cast<const float4*>(g_Wef + k * DD + lane * 4);
        PACK2(w2[k][0], wv.x, wv.y);
        PACK2(w2[k][1], wv.z, wv.w);
    }
    float4 bias = *reinterpret_cast<const float4*>(g_bef + lane * 4);
    uint64_t bias2[2];
    PACK2(bias2[0], bias.x, bias.y);
    PACK2(bias2[1], bias.z, bias.w);

    const int wid = blockIdx.x * 4 + w;
    const int estart = wid * (GPER * CHUNK);
    if (estart >= NE) return;
    const int eend = min(estart + GPER * CHUNK, NE);
    const int nbatch = (eend - estart) / BATCH;

    auto stage = [&](int buf, int ebase) {
#pragma unroll
        for (int i = 0; i < BATCH; i++) {
            int4 e = g_epack4[ebase + i];    // uniform -> broadcast
            uint32_t nfs = (uint32_t)__cvta_generic_to_shared(&wb[buf * 1024 + i * 128 + lane * 4]);
            CPASYNC16(nfs, node + (size_t)e.y * DD + lane * 4);
            if (lane < 4) {
                uint32_t efs = (uint32_t)__cvta_generic_to_shared(&wb[3072 + buf * 128 + i * 16 + lane * 4]);
                CPASYNC16(efs, efeat + (size_t)e.x * EDIM + lane * 4);
            }
            if (lane == 0) dstb[buf * 8 + i] = e.z;
        }
        CPCOMMIT();
    };

    stage(0, estart);
    if (nbatch > 1) stage(1, estart + BATCH);

    float4 acc = make_float4(0.f, 0.f, 0.f, 0.f);
    int prev = -1;

    for (int b = 0; b < nbatch; b++) {
        const int buf = b % 3;
        if (b + 2 < nbatch) {
            stage((b + 2) % 3, estart + (b + 2) * BATCH);
            CPWAIT(2);
        } else if (b + 1 < nbatch) {
            CPWAIT(1);
        } else {
            CPWAIT(0);
        }
        __syncwarp();
        if (b == 0) prev = dstb[0];
#pragma unroll
        for (int i = 0; i < BATCH; i++) {
            int d = dstb[buf * 8 + i];
            if (d != prev) {                  // warp-uniform
                RED4(g_acc + (size_t)prev * DD + lane * 4, acc);
                acc = make_float4(0.f, 0.f, 0.f, 0.f);
                prev = d;
            }
            float4 nf = *reinterpret_cast<const float4*>(&wb[buf * 1024 + i * 128 + lane * 4]);
            const float4* ep = reinterpret_cast<const float4*>(&wb[3072 + buf * 128 + i * 16]);
            float4 f0 = ep[0], f1 = ep[1], f2 = ep[2], f3 = ep[3];  // LDS broadcast
            float ef[EDIM] = {f0.x, f0.y, f0.z, f0.w, f1.x, f1.y, f1.z, f1.w,
                              f2.x, f2.y, f2.z, f2.w, f3.x, f3.y, f3.z, f3.w};
            uint64_t v0, v1, n0, n1;
            PACK2(n0, nf.x, nf.y);
            PACK2(n1, nf.z, nf.w);
            ADD2(v0, bias2[0], n0);
            ADD2(v1, bias2[1], n1);
#pragma unroll
            for (int k = 0; k < EDIM; k++) {
                uint64_t e2;
                PACK2(e2, ef[k], ef[k]);
                FMA2(v0, e2, w2[k][0], v0);
                FMA2(v1, e2, w2[k][1], v1);
            }
            float x, y, z, wv;
            UNPACK2(x, y, v0);
            UNPACK2(z, wv, v1);
            acc.x += fmaxf(x, 0.f);
            acc.y += fmaxf(y, 0.f);
            acc.z += fmaxf(z, 0.f);
            acc.w += fmaxf(wv, 0.f);
        }
    }
    RED4(g_acc + (size_t)prev * DD + lane * 4, acc);
}

// ---------------- tiled fp32 GEMM with packed fp32x2 FMAs ----------------
// rezero=1 (used on the LAST launch) also resets count/cursor for the next call.
__global__ void __launch_bounds__(256) gemm_kernel(const float* __restrict__ A,
                                                   const float* __restrict__ B,
                                                   const float* __restrict__ bias,
                                                   float* __restrict__ C,
                                                   int M, int N, int K, int relu, int rezero) {
    if (rezero) {
        int flat = (blockIdx.y * gridDim.x + blockIdx.x) * 256 + threadIdx.x;
        if (flat < NN) { g_count[flat] = 0; g_cursor[flat] = 0; }
    }

    __shared__ float As[8][128];
    __shared__ float Bs[8][128];

    const int tid = threadIdx.x;
    const int tx = tid % 16;
    const int ty = tid / 16;
    const int m0 = blockIdx.x * 128;
    const int n0 = blockIdx.y * 128;

    const int ar = tid >> 1;
    const int ac = (tid & 1) * 4;
    const int br = tid >> 5;
    const int bc = (tid & 31) * 4;

    uint64_t acc2[8][4];
#pragma unroll
    for (int i = 0; i < 8; i++)
#pragma unroll
        for (int j = 0; j < 4; j++) acc2[i][j] = 0ull;

    for (int k0 = 0; k0 < K; k0 += 8) {
        float4 av = make_float4(0.f, 0.f, 0.f, 0.f);
        if (m0 + ar < M)
            av = *reinterpret_cast<const float4*>(A + (size_t)(m0 + ar) * K + k0 + ac);
        As[ac + 0][ar] = av.x;
        As[ac + 1][ar] = av.y;
        As[ac + 2][ar] = av.z;
        As[ac + 3][ar] = av.w;
        float4 bv = *reinterpret_cast<const float4*>(B + (size_t)(k0 + br) * N + n0 + bc);
        *reinterpret_cast<float4*>(&Bs[br][bc]) = bv;
        __syncthreads();

#pragma unroll
        for (int kk = 0; kk < 8; kk++) {
            float4 a0 = *reinterpret_cast<const float4*>(&As[kk][ty * 8]);
            float4 a1 = *reinterpret_cast<const float4*>(&As[kk][ty * 8 + 4]);
            float4 b0 = *reinterpret_cast<const float4*>(&Bs[kk][tx * 8]);
            float4 b1 = *reinterpret_cast<const float4*>(&Bs[kk][tx * 8 + 4]);
            uint64_t b2[4];
            PACK2(b2[0], b0.x, b0.y);
            PACK2(b2[1], b0.z, b0.w);
            PACK2(b2[2], b1.x, b1.y);
            PACK2(b2[3], b1.z, b1.w);
            float a8[8] = {a0.x, a0.y, a0.z, a0.w, a1.x, a1.y, a1.z, a1.w};
#pragma unroll
            for (int i = 0; i < 8; i++) {
                uint64_t a2;
                PACK2(a2, a8[i], a8[i]);
#pragma unroll
                for (int j = 0; j < 4; j++)
                    FMA2(acc2[i][j], a2, b2[j], acc2[i][j]);
            }
        }
        __syncthreads();
    }

    float bj[8];
#pragma unroll
    for (int j = 0; j < 8; j++) bj[j] = bias[n0 + tx * 8 + j];

#pragma unroll
    for (int i = 0; i < 8; i++) {
        int row = m0 + ty * 8 + i;
        if (row < M) {
            float out[8];
#pragma unroll
            for (int j = 0; j < 4; j++) {
                float lo, hi;
                UNPACK2(lo, hi, acc2[i][j]);
                float v0 = lo + bj[2 * j];
                float v1 = hi + bj[2 * j + 1];
                out[2 * j]     = relu ? fmaxf(v0, 0.f) : v0;
                out[2 * j + 1] = relu ? fmaxf(v1, 0.f) : v1;
            }
            float4* cp = reinterpret_cast<float4*>(C + (size_t)row * N + n0 + tx * 8);
            cp[0] = make_float4(out[0], out[1], out[2], out[3]);
            cp[1] = make_float4(out[4], out[5], out[6], out[7]);
        }
    }
}

// ---------------- launch ----------------
extern "C" void kernel_launch(void* const* d_in, const int* in_sizes, int n_in,
                              void* d_out, int out_size) {
    const float* node  = (const float*)d_in[0];
    const float* efeat = (const float*)d_in[1];
    const int*   src   = (const int*)d_in[2];
    const int*   dst   = (const int*)d_in[3];
    const float* We1 = (const float*)d_in[4];
    const float* be1 = (const float*)d_in[5];
    const float* We2 = (const float*)d_in[6];
    const float* be2 = (const float*)d_in[7];
    const float* eps = (const float*)d_in[8];
    const float* Wm1 = (const float*)d_in[9];
    const float* bm1 = (const float*)d_in[10];
    const float* g1  = (const float*)d_in[11];
    const float* b1  = (const float*)d_in[12];
    const float* m1  = (const float*)d_in[13];
    const float* v1  = (const float*)d_in[14];
    const float* Wm2 = (const float*)d_in[15];
    const float* bm2 = (const float*)d_in[16];
    const float* g2  = (const float*)d_in[17];
    const float* b2  = (const float*)d_in[18];
    const float* m2  = (const float*)d_in[19];
    const float* v2  = (const float*)d_in[20];
    float* out = (float*)d_out;

    // L1: prep (128 blocks) + hist (3125 blocks)
    prep_hist_kernel<<<128 + (NE + 255) / 256, 256>>>(
        We1, be1, We2, be2, Wm1, bm1, g1, b1, m1, v1,
        Wm2, bm2, g2, b2, m2, v2, dst);
    // L2
    scan1_kernel<<<NB, 1024>>>();
    // L3: init (6250 blocks) + scatter (3125 blocks)
    scatter_init_kernel<<<INIT_BLOCKS + (NE + 255) / 256, 256>>>(
        src, dst, (const float4*)node, eps);
    // L4: accum (profiled launch)
    static int smem_set = 0;
    if (!smem_set) {
        cudaFuncSetAttribute(accum_kernel, cudaFuncAttributeMaxDynamicSharedMemorySize, ACC_SMEM);
        smem_set = 1;
    }
    accum_kernel<<<ACC_BLOCKS, dim3(32, 4), ACC_SMEM>>>(node, efeat);

    float *pacc, *pt, *pW1, *pb1, *pW2, *pb2;
    cudaGetSymbolAddress((void**)&pacc, g_acc);
    cudaGetSymbolAddress((void**)&pt,   g_t);
    cudaGetSymbolAddress((void**)&pW1,  g_W1);
    cudaGetSymbolAddress((void**)&pb1,  g_b1);
    cudaGetSymbolAddress((void**)&pW2,  g_W2);
    cudaGetSymbolAddress((void**)&pb2,  g_b2);

    // L5 / L6 (L6 re-zeros count/cursor for the next call)
    gemm_kernel<<<dim3((NN + 127) / 128, 256 / 128), 256>>>(pacc, pW1, pb1, pt,
                                                            NN, 256, DD, 1, 0);
    gemm_kernel<<<dim3((NN + 127) / 128, DD / 128), 256>>>(pt, pW2, pb2, out,
                                                           NN, DD, 256, 0, 1);
}

// round 12
// speedup vs baseline: 1.0240x; 1.0240x over previous
#include <cuda_runtime.h>
#include <cstdint>

#define NN 50000
#define DD 128
#define EDIM 16
#define NE 800000
#define NB 49        // ceil(NN/1024)
#define CHUNK 16
#define BATCH 8
#define NCHUNK (NE / CHUNK)   // 50000

#define ACC_BLOCKS 740
#define ACC_WARPS (ACC_BLOCKS * 4)                    // 2960
#define GPER ((NCHUNK + ACC_WARPS - 1) / ACC_WARPS)   // 17 chunks -> 272 edges/warp

// dynamic smem layout (per warp, in 4-byte words), 2 buffers:
//  nf: 2 bufs * 8 edges * 128 ch = 2048
//  ef: 2 bufs * 8 edges * 16    = 256   (offset 2048)
#define WARP_WORDS 2304
#define ACC_SMEM (4 * WARP_WORDS * 4)                 // 36864 bytes

// packed fp32x2 helpers (Blackwell FFMA2 path)
#define PACK2(d, lo, hi)  asm("mov.b64 %0, {%1, %2};" : "=l"(d) : "f"(lo), "f"(hi))
#define UNPACK2(lo, hi, s) asm("mov.b64 {%0, %1}, %2;" : "=f"(lo), "=f"(hi) : "l"(s))
#define FMA2(d, a, b, c)  asm("fma.rn.f32x2 %0, %1, %2, %3;" : "=l"(d) : "l"(a), "l"(b), "l"(c))
#define ADD2(d, a, b)     asm("add.rn.f32x2 %0, %1, %2;" : "=l"(d) : "l"(a), "l"(b))
#define RED4(p, v) asm volatile("red.global.add.v4.f32 [%0], {%1, %2, %3, %4};" \
                                :: "l"(p), "f"((v).x), "f"((v).y), "f"((v).z), "f"((v).w) : "memory")
#define CPASYNC16(sm, gp) asm volatile("cp.async.ca.shared.global [%0], [%1], 16;" \
                                       :: "r"(sm), "l"(gp) : "memory")
#define CPCOMMIT() asm volatile("cp.async.commit_group;" ::: "memory")
#define CPWAIT(n)  asm volatile("cp.async.wait_group %0;" :: "n"(n) : "memory")

// ---------------- device scratch ----------------
__device__ float g_Wef[EDIM * DD];
__device__ float g_bef[DD];
__device__ float g_W1[DD * 256];
__device__ float g_b1[256];
__device__ float g_W2[256 * DD];
__device__ float g_b2[DD];
__device__ float g_acc[(size_t)NN * DD];
__device__ float g_t[(size_t)NN * 256];
__device__ int   g_count[NN];     // zero at entry (static init / re-zeroed by gemm2)
__device__ int   g_cursor[NN];    // zero at entry (same)
__device__ int   g_csum[NN];      // per-tile inclusive scan (no global offset)
__device__ int   g_bsum[64];
__device__ int4  g_epack4[NE];    // sorted by dst: (edge_id, src, dst, 0)

// ---------------- L1: prep (blocks 0..127) + hist (blocks 128..) ----------------
__global__ void prep_hist_kernel(const float* __restrict__ We1, const float* __restrict__ be1,
                                 const float* __restrict__ We2, const float* __restrict__ be2,
                                 const float* __restrict__ Wm1, const float* __restrict__ bm1,
                                 const float* __restrict__ g1, const float* __restrict__ b1,
                                 const float* __restrict__ m1, const float* __restrict__ v1,
                                 const float* __restrict__ Wm2, const float* __restrict__ bm2,
                                 const float* __restrict__ g2, const float* __restrict__ b2,
                                 const float* __restrict__ m2, const float* __restrict__ v2,
                                 const int* __restrict__ dst) {
    if (blockIdx.x >= 128) {
        int e = (blockIdx.x - 128) * 256 + threadIdx.x;
        if (e < NE) atomicAdd(&g_count[dst[e]], 1);
        return;
    }
    int i = blockIdx.x * 256 + threadIdx.x;   // 0..32767

    if (i < EDIM * DD) {
        int k = i / DD, d = i % DD;
        float s = 0.f;
        for (int j = 0; j < 256; j++) s += We1[k * 256 + j] * We2[j * DD + d];
        g_Wef[i] = s;
    }
    if (i < DD) {
        float s = be2[i];
        for (int j = 0; j < 256; j++) s += be1[j] * We2[j * DD + i];
        g_bef[i] = s;
    }
    if (i < DD * 256) {
        int j = i % 256;
        float a = g1[j] * rsqrtf(v1[j] + 1e-3f);
        g_W1[i] = Wm1[i] * a;
    }
    if (i < 256) {
        float a = g1[i] * rsqrtf(v1[i] + 1e-3f);
        g_b1[i] = bm1[i] * a + b1[i] - m1[i] * a;
    }
    if (i < 256 * DD) {
        int j = i % DD;
        float a = g2[j] * rsqrtf(v2[j] + 1e-3f);
        g_W2[i] = Wm2[i] * a;
    }
    if (i < DD) {
        float a = g2[i] * rsqrtf(v2[i] + 1e-3f);
        g_b2[i] = bm2[i] * a + b2[i] - m2[i] * a;
    }
}

// ---------------- L2: per-tile inclusive scan + block sums ----------------
__global__ void scan1_kernel() {
    __shared__ int sm[1024];
    int i = blockIdx.x * 1024 + threadIdx.x;
    int v = (i < NN) ? g_count[i] : 0;
    sm[threadIdx.x] = v;
    __syncthreads();
    for (int off = 1; off < 1024; off <<= 1) {
        int add = (threadIdx.x >= off) ? sm[threadIdx.x - off] : 0;
        __syncthreads();
        sm[threadIdx.x] += add;
        __syncthreads();
    }
    if (i < NN) g_csum[i] = sm[threadIdx.x];
    if (threadIdx.x == 1023) g_bsum[blockIdx.x] = sm[1023];
}

// ---------------- L3: init_acc (blocks 0..6249) + scatter (blocks 6250..) ----------------
#define INIT_BLOCKS 6250   // 1,600,000 float4 / 256
__global__ void scatter_init_kernel(const int* __restrict__ src, const int* __restrict__ dst,
                                    const float4* __restrict__ node4,
                                    const float* __restrict__ eps) {
    if (blockIdx.x < INIT_BLOCKS) {
        int i = blockIdx.x * 256 + threadIdx.x;
        float s = 1.f + eps[0];
        float4 v = node4[i];
        v.x *= s; v.y *= s; v.z *= s; v.w *= s;
        reinterpret_cast<float4*>(g_acc)[i] = v;
        return;
    }
    int i = (blockIdx.x - INIT_BLOCKS) * 256 + threadIdx.x;
    if (i < NE) {
        int t = dst[i];
        int tb = t >> 10;
        int off = 0;
        for (int j = 0; j < tb; j++) off += g_bsum[j];
        int beg = g_csum[t] + off - g_count[t];
        int pos = beg + atomicAdd(&g_cursor[t], 1);
        g_epack4[pos] = make_int4(i, src[i], t, 0);
    }
}

// ---------------- L4: persistent 2-buffer cp.async segmented accumulation ----------------
// dst ids kept in registers (lane i holds edge i's dst), read via shfl.
__global__ void __launch_bounds__(128) accum_kernel(const float* __restrict__ node,
                                                    const float* __restrict__ efeat) {
    extern __shared__ float dsm[];
    const int lane = threadIdx.x;
    const int w = threadIdx.y;
    float* wb = dsm + w * WARP_WORDS;

    uint64_t w2[EDIM][2];
#pragma unroll
    for (int k = 0; k < EDIM; k++) {
        float4 wv = *reinterpret_cast<const float4*>(g_Wef + k * DD + lane * 4);
        PACK2(w2[k][0], wv.x, wv.y);
        PACK2(w2[k][1], wv.z, wv.w);
    }
    float4 bias = *reinterpret_cast<const float4*>(g_bef + lane * 4);
    uint64_t bias2[2];
    PACK2(bias2[0], bias.x, bias.y);
    PACK2(bias2[1], bias.z, bias.w);

    const int wid = blockIdx.x * 4 + w;
    const int estart = wid * (GPER * CHUNK);
    if (estart >= NE) return;
    const int eend = min(estart + GPER * CHUNK, NE);
    const int nbatch = (eend - estart) / BATCH;

    int dreg[2];   // lane i (<8) holds dst of edge i of the staged batch

    auto stage = [&](int buf, int ebase) {
#pragma unroll
        for (int i = 0; i < BATCH; i++) {
            int4 e = g_epack4[ebase + i];    // uniform -> broadcast
            uint32_t nfs = (uint32_t)__cvta_generic_to_shared(&wb[buf * 1024 + i * 128 + lane * 4]);
            CPASYNC16(nfs, node + (size_t)e.y * DD + lane * 4);
            if (lane < 4) {
                uint32_t efs = (uint32_t)__cvta_generic_to_shared(&wb[2048 + buf * 128 + i * 16 + lane * 4]);
                CPASYNC16(efs, efeat + (size_t)e.x * EDIM + lane * 4);
            }
            if (lane == i) dreg[buf] = e.z;
        }
        CPCOMMIT();
    };

    stage(0, estart);

    float4 acc = make_float4(0.f, 0.f, 0.f, 0.f);
    int prev = -1;

    for (int b = 0; b < nbatch; b++) {
        const int buf = b & 1;
        if (b + 1 < nbatch) {
            stage(buf ^ 1, estart + (b + 1) * BATCH);
            CPWAIT(1);                        // batch b ready, b+1 in flight
        } else {
            CPWAIT(0);
        }
        __syncwarp();
        if (b == 0) prev = __shfl_sync(0xffffffffu, dreg[0], 0);
#pragma unroll
        for (int i = 0; i < BATCH; i++) {
            int d = __shfl_sync(0xffffffffu, dreg[buf], i);
            if (d != prev) {                  // warp-uniform
                RED4(g_acc + (size_t)prev * DD + lane * 4, acc);
                acc = make_float4(0.f, 0.f, 0.f, 0.f);
                prev = d;
            }
            float4 nf = *reinterpret_cast<const float4*>(&wb[buf * 1024 + i * 128 + lane * 4]);
            const float4* ep = reinterpret_cast<const float4*>(&wb[2048 + buf * 128 + i * 16]);
            float4 f0 = ep[0], f1 = ep[1], f2 = ep[2], f3 = ep[3];  // LDS broadcast
            float ef[EDIM] = {f0.x, f0.y, f0.z, f0.w, f1.x, f1.y, f1.z, f1.w,
                              f2.x, f2.y, f2.z, f2.w, f3.x, f3.y, f3.z, f3.w};
            uint64_t v0, v1, n0, n1;
            PACK2(n0, nf.x, nf.y);
            PACK2(n1, nf.z, nf.w);
            ADD2(v0, bias2[0], n0);
            ADD2(v1, bias2[1], n1);
#pragma unroll
            for (int k = 0; k < EDIM; k++) {
                uint64_t e2;
                PACK2(e2, ef[k], ef[k]);
                FMA2(v0, e2, w2[k][0], v0);
                FMA2(v1, e2, w2[k][1], v1);
            }
            float x, y, z, wv;
            UNPACK2(x, y, v0);
            UNPACK2(z, wv, v1);
            acc.x += fmaxf(x, 0.f);
            acc.y += fmaxf(y, 0.f);
            acc.z += fmaxf(z, 0.f);
            acc.w += fmaxf(wv, 0.f);
        }
    }
    RED4(g_acc + (size_t)prev * DD + lane * 4, acc);
}

// ---------------- tiled fp32 GEMM with packed fp32x2 FMAs ----------------
// rezero=1 (used on the LAST launch) also resets count/cursor for the next call.
__global__ void __launch_bounds__(256) gemm_kernel(const float* __restrict__ A,
                                                   const float* __restrict__ B,
                                                   const float* __restrict__ bias,
                                                   float* __restrict__ C,
                                                   int M, int N, int K, int relu, int rezero) {
    if (rezero) {
        int flat = (blockIdx.y * gridDim.x + blockIdx.x) * 256 + threadIdx.x;
        if (flat < NN) { g_count[flat] = 0; g_cursor[flat] = 0; }
    }

    __shared__ float As[8][128];
    __shared__ float Bs[8][128];

    const int tid = threadIdx.x;
    const int tx = tid % 16;
    const int ty = tid / 16;
    const int m0 = blockIdx.x * 128;
    const int n0 = blockIdx.y * 128;

    const int ar = tid >> 1;
    const int ac = (tid & 1) * 4;
    const int br = tid >> 5;
    const int bc = (tid & 31) * 4;

    uint64_t acc2[8][4];
#pragma unroll
    for (int i = 0; i < 8; i++)
#pragma unroll
        for (int j = 0; j < 4; j++) acc2[i][j] = 0ull;

    for (int k0 = 0; k0 < K; k0 += 8) {
        float4 av = make_float4(0.f, 0.f, 0.f, 0.f);
        if (m0 + ar < M)
            av = *reinterpret_cast<const float4*>(A + (size_t)(m0 + ar) * K + k0 + ac);
        As[ac + 0][ar] = av.x;
        As[ac + 1][ar] = av.y;
        As[ac + 2][ar] = av.z;
        As[ac + 3][ar] = av.w;
        float4 bv = *reinterpret_cast<const float4*>(B + (size_t)(k0 + br) * N + n0 + bc);
        *reinterpret_cast<float4*>(&Bs[br][bc]) = bv;
        __syncthreads();

#pragma unroll
        for (int kk = 0; kk < 8; kk++) {
            float4 a0 = *reinterpret_cast<const float4*>(&As[kk][ty * 8]);
            float4 a1 = *reinterpret_cast<const float4*>(&As[kk][ty * 8 + 4]);
            float4 b0 = *reinterpret_cast<const float4*>(&Bs[kk][tx * 8]);
            float4 b1 = *reinterpret_cast<const float4*>(&Bs[kk][tx * 8 + 4]);
            uint64_t b2[4];
            PACK2(b2[0], b0.x, b0.y);
            PACK2(b2[1], b0.z, b0.w);
            PACK2(b2[2], b1.x, b1.y);
            PACK2(b2[3], b1.z, b1.w);
            float a8[8] = {a0.x, a0.y, a0.z, a0.w, a1.x, a1.y, a1.z, a1.w};
#pragma unroll
            for (int i = 0; i < 8; i++) {
                uint64_t a2;
                PACK2(a2, a8[i], a8[i]);
#pragma unroll
                for (int j = 0; j < 4; j++)
                    FMA2(acc2[i][j], a2, b2[j], acc2[i][j]);
            }
        }
        __syncthreads();
    }

    float bj[8];
#pragma unroll
    for (int j = 0; j < 8; j++) bj[j] = bias[n0 + tx * 8 + j];

#pragma unroll
    for (int i = 0; i < 8; i++) {
        int row = m0 + ty * 8 + i;
        if (row < M) {
            float out[8];
#pragma unroll
            for (int j = 0; j < 4; j++) {
                float lo, hi;
                UNPACK2(lo, hi, acc2[i][j]);
                float v0 = lo + bj[2 * j];
                float v1 = hi + bj[2 * j + 1];
                out[2 * j]     = relu ? fmaxf(v0, 0.f) : v0;
                out[2 * j + 1] = relu ? fmaxf(v1, 0.f) : v1;
            }
            float4* cp = reinterpret_cast<float4*>(C + (size_t)row * N + n0 + tx * 8);
            cp[0] = make_float4(out[0], out[1], out[2], out[3]);
            cp[1] = make_float4(out[4], out[5], out[6], out[7]);
        }
    }
}

// ---------------- launch ----------------
extern "C" void kernel_launch(void* const* d_in, const int* in_sizes, int n_in,
                              void* d_out, int out_size) {
    const float* node  = (const float*)d_in[0];
    const float* efeat = (const float*)d_in[1];
    const int*   src   = (const int*)d_in[2];
    const int*   dst   = (const int*)d_in[3];
    const float* We1 = (const float*)d_in[4];
    const float* be1 = (const float*)d_in[5];
    const float* We2 = (const float*)d_in[6];
    const float* be2 = (const float*)d_in[7];
    const float* eps = (const float*)d_in[8];
    const float* Wm1 = (const float*)d_in[9];
    const float* bm1 = (const float*)d_in[10];
    const float* g1  = (const float*)d_in[11];
    const float* b1  = (const float*)d_in[12];
    const float* m1  = (const float*)d_in[13];
    const float* v1  = (const float*)d_in[14];
    const float* Wm2 = (const float*)d_in[15];
    const float* bm2 = (const float*)d_in[16];
    const float* g2  = (const float*)d_in[17];
    const float* b2  = (const float*)d_in[18];
    const float* m2  = (const float*)d_in[19];
    const float* v2  = (const float*)d_in[20];
    float* out = (float*)d_out;

    // L1: prep (128 blocks) + hist (3125 blocks)
    prep_hist_kernel<<<128 + (NE + 255) / 256, 256>>>(
        We1, be1, We2, be2, Wm1, bm1, g1, b1, m1, v1,
        Wm2, bm2, g2, b2, m2, v2, dst);
    // L2
    scan1_kernel<<<NB, 1024>>>();
    // L3: init (6250 blocks) + scatter (3125 blocks)
    scatter_init_kernel<<<INIT_BLOCKS + (NE + 255) / 256, 256>>>(
        src, dst, (const float4*)node, eps);
    // L4: accum (profiled launch)
    accum_kernel<<<ACC_BLOCKS, dim3(32, 4), ACC_SMEM>>>(node, efeat);

    float *pacc, *pt, *pW1, *pb1, *pW2, *pb2;
    cudaGetSymbolAddress((void**)&pacc, g_acc);
    cudaGetSymbolAddress((void**)&pt,   g_t);
    cudaGetSymbolAddress((void**)&pW1,  g_W1);
    cudaGetSymbolAddress((void**)&pb1,  g_b1);
    cudaGetSymbolAddress((void**)&pW2,  g_W2);
    cudaGetSymbolAddress((void**)&pb2,  g_b2);

    // L5 / L6 (L6 re-zeros count/cursor for the next call)
    gemm_kernel<<<dim3((NN + 127) / 128, 256 / 128), 256>>>(pacc, pW1, pb1, pt,
                                                            NN, 256, DD, 1, 0);
    gemm_kernel<<<dim3((NN + 127) / 128, DD / 128), 256>>>(pt, pW2, pb2, out,
                                                           NN, DD, 256, 0, 1);
}

// round 14
// speedup vs baseline: 1.0741x; 1.0489x over previous
#include <cuda_runtime.h>
#include <cstdint>

#define NN 50000
#define DD 128
#define EDIM 16
#define NE 800000
#define NB 49        // ceil(NN/1024)
#define CHUNK 16
#define BATCH 8
#define NCHUNK (NE / CHUNK)   // 50000

#define ACC_BLOCKS 740
#define ACC_WARPS (ACC_BLOCKS * 4)                    // 2960
#define GPER ((NCHUNK + ACC_WARPS - 1) / ACC_WARPS)   // 17 chunks -> 272 edges/warp

// dynamic smem layout (per warp, in 4-byte words), 2 buffers:
//  nf:  2 bufs * 8 edges * 128 ch = 2048
//  ef:  2 bufs * 8 edges * 16     = 256   (offset 2048)
//  dst: 2 bufs * 8                = 16    (offset 2304)
#define WARP_WORDS 2320
#define ACC_SMEM (4 * WARP_WORDS * 4)                 // 37120 bytes

// packed fp32x2 helpers (Blackwell FFMA2 path)
#define PACK2(d, lo, hi)  asm("mov.b64 %0, {%1, %2};" : "=l"(d) : "f"(lo), "f"(hi))
#define UNPACK2(lo, hi, s) asm("mov.b64 {%0, %1}, %2;" : "=f"(lo), "=f"(hi) : "l"(s))
#define FMA2(d, a, b, c)  asm("fma.rn.f32x2 %0, %1, %2, %3;" : "=l"(d) : "l"(a), "l"(b), "l"(c))
#define ADD2(d, a, b)     asm("add.rn.f32x2 %0, %1, %2;" : "=l"(d) : "l"(a), "l"(b))
#define RED4(p, v) asm volatile("red.global.add.v4.f32 [%0], {%1, %2, %3, %4};" \
                                :: "l"(p), "f"((v).x), "f"((v).y), "f"((v).z), "f"((v).w) : "memory")
#define CPASYNC16(sm, gp) asm volatile("cp.async.ca.shared.global [%0], [%1], 16;" \
                                       :: "r"(sm), "l"(gp) : "memory")
#define CPCOMMIT() asm volatile("cp.async.commit_group;" ::: "memory")
#define CPWAIT(n)  asm volatile("cp.async.wait_group %0;" :: "n"(n) : "memory")

// ---------------- device scratch ----------------
__device__ float g_Wef[EDIM * DD];
__device__ float g_bef[DD];
__device__ float g_W1[DD * 256];
__device__ float g_b1[256];
__device__ float g_W2[256 * DD];
__device__ float g_b2[DD];
__device__ float g_acc[(size_t)NN * DD];
__device__ float g_t[(size_t)NN * 256];
__device__ int   g_count[NN];     // zero at entry (static init / re-zeroed by gemm2)
__device__ int   g_cursor[NN];    // zero at entry (same)
__device__ int   g_csum[NN];      // per-tile inclusive scan (no global offset)
__device__ int   g_bsum[64];
__device__ int4  g_epack4[NE];    // sorted by dst: (edge_id, src, dst, 0)

// ---------------- L1: prep (blocks 0..127) + hist (blocks 128..) ----------------
__global__ void prep_hist_kernel(const float* __restrict__ We1, const float* __restrict__ be1,
                                 const float* __restrict__ We2, const float* __restrict__ be2,
                                 const float* __restrict__ Wm1, const float* __restrict__ bm1,
                                 const float* __restrict__ g1, const float* __restrict__ b1,
                                 const float* __restrict__ m1, const float* __restrict__ v1,
                                 const float* __restrict__ Wm2, const float* __restrict__ bm2,
                                 const float* __restrict__ g2, const float* __restrict__ b2,
                                 const float* __restrict__ m2, const float* __restrict__ v2,
                                 const int* __restrict__ dst) {
    if (blockIdx.x >= 128) {
        int e = (blockIdx.x - 128) * 256 + threadIdx.x;
        if (e < NE) atomicAdd(&g_count[dst[e]], 1);
        return;
    }
    int i = blockIdx.x * 256 + threadIdx.x;   // 0..32767

    if (i < EDIM * DD) {
        int k = i / DD, d = i % DD;
        float s = 0.f;
        for (int j = 0; j < 256; j++) s += We1[k * 256 + j] * We2[j * DD + d];
        g_Wef[i] = s;
    }
    if (i < DD) {
        float s = be2[i];
        for (int j = 0; j < 256; j++) s += be1[j] * We2[j * DD + i];
        g_bef[i] = s;
    }
    if (i < DD * 256) {
        int j = i % 256;
        float a = g1[j] * rsqrtf(v1[j] + 1e-3f);
        g_W1[i] = Wm1[i] * a;
    }
    if (i < 256) {
        float a = g1[i] * rsqrtf(v1[i] + 1e-3f);
        g_b1[i] = bm1[i] * a + b1[i] - m1[i] * a;
    }
    if (i < 256 * DD) {
        int j = i % DD;
        float a = g2[j] * rsqrtf(v2[j] + 1e-3f);
        g_W2[i] = Wm2[i] * a;
    }
    if (i < DD) {
        float a = g2[i] * rsqrtf(v2[i] + 1e-3f);
        g_b2[i] = bm2[i] * a + b2[i] - m2[i] * a;
    }
}

// ---------------- L2: per-tile inclusive scan + block sums ----------------
__global__ void scan1_kernel() {
    __shared__ int sm[1024];
    int i = blockIdx.x * 1024 + threadIdx.x;
    int v = (i < NN) ? g_count[i] : 0;
    sm[threadIdx.x] = v;
    __syncthreads();
    for (int off = 1; off < 1024; off <<= 1) {
        int add = (threadIdx.x >= off) ? sm[threadIdx.x - off] : 0;
        __syncthreads();
        sm[threadIdx.x] += add;
        __syncthreads();
    }
    if (i < NN) g_csum[i] = sm[threadIdx.x];
    if (threadIdx.x == 1023) g_bsum[blockIdx.x] = sm[1023];
}

// ---------------- L3: init_acc (blocks 0..6249) + scatter (blocks 6250..) ----------------
#define INIT_BLOCKS 6250   // 1,600,000 float4 / 256
__global__ void scatter_init_kernel(const int* __restrict__ src, const int* __restrict__ dst,
                                    const float4* __restrict__ node4,
                                    const float* __restrict__ eps) {
    if (blockIdx.x < INIT_BLOCKS) {
        int i = blockIdx.x * 256 + threadIdx.x;
        float s = 1.f + eps[0];
        float4 v = node4[i];
        v.x *= s; v.y *= s; v.z *= s; v.w *= s;
        reinterpret_cast<float4*>(g_acc)[i] = v;
        return;
    }
    // inclusive prefix of g_bsum in shared — ALL threads execute every barrier
    __shared__ int soff[64];
    const int tid = threadIdx.x;
    if (tid < 64) soff[tid] = (tid < NB) ? g_bsum[tid] : 0;
    __syncthreads();
#pragma unroll
    for (int off = 1; off < 64; off <<= 1) {
        int add = 0;
        if (tid < 64 && tid >= off) add = soff[tid - off];
        __syncthreads();
        if (tid < 64) soff[tid] += add;
        __syncthreads();
    }
    int i = (blockIdx.x - INIT_BLOCKS) * 256 + tid;
    if (i < NE) {
        int t = dst[i];
        int tb = t >> 10;
        int off = (tb > 0) ? soff[tb - 1] : 0;   // exclusive offset of tile tb
        int beg = g_csum[t] + off - g_count[t];
        int pos = beg + atomicAdd(&g_cursor[t], 1);
        g_epack4[pos] = make_int4(i, src[i], t, 0);
    }
}

// ---------------- L4: persistent 2-buffer cp.async segmented accumulation ----------------
__global__ void __launch_bounds__(128) accum_kernel(const float* __restrict__ node,
                                                    const float* __restrict__ efeat) {
    extern __shared__ float dsm[];
    const int lane = threadIdx.x;
    const int w = threadIdx.y;
    float* wb = dsm + w * WARP_WORDS;
    int* dstb = reinterpret_cast<int*>(wb + 2304);

    uint64_t w2[EDIM][2];
#pragma unroll
    for (int k = 0; k < EDIM; k++) {
        float4 wv = *reinterpret_cast<const float4*>(g_Wef + k * DD + lane * 4);
        PACK2(w2[k][0], wv.x, wv.y);
        PACK2(w2[k][1], wv.z, wv.w);
    }
    float4 bias = *reinterpret_cast<const float4*>(g_bef + lane * 4);
    uint64_t bias2[2];
    PACK2(bias2[0], bias.x, bias.y);
    PACK2(bias2[1], bias.z, bias.w);

    const int wid = blockIdx.x * 4 + w;
    const int estart = wid * (GPER * CHUNK);
    if (estart >= NE) return;
    const int eend = min(estart + GPER * CHUNK, NE);
    const int nbatch = (eend - estart) / BATCH;

    auto stage = [&](int buf, int ebase) {
#pragma unroll
        for (int i = 0; i < BATCH; i++) {
            int4 e = g_epack4[ebase + i];    // uniform -> broadcast
            uint32_t nfs = (uint32_t)__cvta_generic_to_shared(&wb[buf * 1024 + i * 128 + lane * 4]);
            CPASYNC16(nfs, node + (size_t)e.y * DD + lane * 4);
            if (lane < 4) {
                uint32_t efs = (uint32_t)__cvta_generic_to_shared(&wb[2048 + buf * 128 + i * 16 + lane * 4]);
                CPASYNC16(efs, efeat + (size_t)e.x * EDIM + lane * 4);
            }
            if (lane == 0) dstb[buf * 8 + i] = e.z;
        }
        CPCOMMIT();
    };

    stage(0, estart);

    float4 acc = make_float4(0.f, 0.f, 0.f, 0.f);
    int prev = -1;

    for (int b = 0; b < nbatch; b++) {
        const int buf = b & 1;
        if (b + 1 < nbatch) {
            stage(buf ^ 1, estart + (b + 1) * BATCH);
            CPWAIT(1);                        // batch b ready, b+1 in flight
        } else {
            CPWAIT(0);
        }
        __syncwarp();
        if (b == 0) prev = dstb[0];
#pragma unroll
        for (int i = 0; i < BATCH; i++) {
            int d = dstb[buf * 8 + i];        // LDS broadcast
            if (d != prev) {                  // warp-uniform
                RED4(g_acc + (size_t)prev * DD + lane * 4, acc);
                acc = make_float4(0.f, 0.f, 0.f, 0.f);
                prev = d;
            }
            float4 nf = *reinterpret_cast<const float4*>(&wb[buf * 1024 + i * 128 + lane * 4]);
            const float4* ep = reinterpret_cast<const float4*>(&wb[2048 + buf * 128 + i * 16]);
            float4 f0 = ep[0], f1 = ep[1], f2 = ep[2], f3 = ep[3];  // LDS broadcast
            float ef[EDIM] = {f0.x, f0.y, f0.z, f0.w, f1.x, f1.y, f1.z, f1.w,
                              f2.x, f2.y, f2.z, f2.w, f3.x, f3.y, f3.z, f3.w};
            uint64_t v0, v1, n0, n1;
            PACK2(n0, nf.x, nf.y);
            PACK2(n1, nf.z, nf.w);
            ADD2(v0, bias2[0], n0);
            ADD2(v1, bias2[1], n1);
#pragma unroll
            for (int k = 0; k < EDIM; k++) {
                uint64_t e2;
                PACK2(e2, ef[k], ef[k]);
                FMA2(v0, e2, w2[k][0], v0);
                FMA2(v1, e2, w2[k][1], v1);
            }
            float x, y, z, wv;
            UNPACK2(x, y, v0);
            UNPACK2(z, wv, v1);
            acc.x += fmaxf(x, 0.f);
            acc.y += fmaxf(y, 0.f);
            acc.z += fmaxf(z, 0.f);
            acc.w += fmaxf(wv, 0.f);
        }
    }
    RED4(g_acc + (size_t)prev * DD + lane * 4, acc);
}

// ---------------- tiled fp32 GEMM with packed fp32x2 FMAs ----------------
// rezero=1 (used on the LAST launch) also resets count/cursor for the next call.
__global__ void __launch_bounds__(256) gemm_kernel(const float* __restrict__ A,
                                                   const float* __restrict__ B,
                                                   const float* __restrict__ bias,
                                                   float* __restrict__ C,
                                                   int M, int N, int K, int relu, int rezero) {
    if (rezero) {
        int flat = (blockIdx.y * gridDim.x + blockIdx.x) * 256 + threadIdx.x;
        if (flat < NN) { g_count[flat] = 0; g_cursor[flat] = 0; }
    }

    __shared__ float As[8][128];
    __shared__ float Bs[8][128];

    const int tid = threadIdx.x;
    const int tx = tid % 16;
    const int ty = tid / 16;
    const int m0 = blockIdx.x * 128;
    const int n0 = blockIdx.y * 128;

    const int ar = tid >> 1;
    const int ac = (tid & 1) * 4;
    const int br = tid >> 5;
    const int bc = (tid & 31) * 4;

    uint64_t acc2[8][4];
#pragma unroll
    for (int i = 0; i < 8; i++)
#pragma unroll
        for (int j = 0; j < 4; j++) acc2[i][j] = 0ull;

    for (int k0 = 0; k0 < K; k0 += 8) {
        float4 av = make_float4(0.f, 0.f, 0.f, 0.f);
        if (m0 + ar < M)
            av = *reinterpret_cast<const float4*>(A + (size_t)(m0 + ar) * K + k0 + ac);
        As[ac + 0][ar] = av.x;
        As[ac + 1][ar] = av.y;
        As[ac + 2][ar] = av.z;
        As[ac + 3][ar] = av.w;
        float4 bv = *reinterpret_cast<const float4*>(B + (size_t)(k0 + br) * N + n0 + bc);
        *reinterpret_cast<float4*>(&Bs[br][bc]) = bv;
        __syncthreads();

#pragma unroll
        for (int kk = 0; kk < 8; kk++) {
            float4 a0 = *reinterpret_cast<const float4*>(&As[kk][ty * 8]);
            float4 a1 = *reinterpret_cast<const float4*>(&As[kk][ty * 8 + 4]);
            float4 b0 = *reinterpret_cast<const float4*>(&Bs[kk][tx * 8]);
            float4 b1 = *reinterpret_cast<const float4*>(&Bs[kk][tx * 8 + 4]);
            uint64_t b2[4];
            PACK2(b2[0], b0.x, b0.y);
            PACK2(b2[1], b0.z, b0.w);
            PACK2(b2[2], b1.x, b1.y);
            PACK2(b2[3], b1.z, b1.w);
            float a8[8] = {a0.x, a0.y, a0.z, a0.w, a1.x, a1.y, a1.z, a1.w};
#pragma unroll
            for (int i = 0; i < 8; i++) {
                uint64_t a2;
                PACK2(a2, a8[i], a8[i]);
#pragma unroll
                for (int j = 0; j < 4; j++)
                    FMA2(acc2[i][j], a2, b2[j], acc2[i][j]);
            }
        }
        __syncthreads();
    }

    float bj[8];
#pragma unroll
    for (int j = 0; j < 8; j++) bj[j] = bias[n0 + tx * 8 + j];

#pragma unroll
    for (int i = 0; i < 8; i++) {
        int row = m0 + ty * 8 + i;
        if (row < M) {
            float out[8];
#pragma unroll
            for (int j = 0; j < 4; j++) {
                float lo, hi;
                UNPACK2(lo, hi, acc2[i][j]);
                float v0 = lo + bj[2 * j];
                float v1 = hi + bj[2 * j + 1];
                out[2 * j]     = relu ? fmaxf(v0, 0.f) : v0;
                out[2 * j + 1] = relu ? fmaxf(v1, 0.f) : v1;
            }
            float4* cp = reinterpret_cast<float4*>(C + (size_t)row * N + n0 + tx * 8);
            cp[0] = make_float4(out[0], out[1], out[2], out[3]);
            cp[1] = make_float4(out[4], out[5], out[6], out[7]);
        }
    }
}

// ---------------- launch ----------------
extern "C" void kernel_launch(void* const* d_in, const int* in_sizes, int n_in,
                              void* d_out, int out_size) {
    const float* node  = (const float*)d_in[0];
    const float* efeat = (const float*)d_in[1];
    const int*   src   = (const int*)d_in[2];
    const int*   dst   = (const int*)d_in[3];
    const float* We1 = (const float*)d_in[4];
    const float* be1 = (const float*)d_in[5];
    const float* We2 = (const float*)d_in[6];
    const float* be2 = (const float*)d_in[7];
    const float* eps = (const float*)d_in[8];
    const float* Wm1 = (const float*)d_in[9];
    const float* bm1 = (const float*)d_in[10];
    const float* g1  = (const float*)d_in[11];
    const float* b1  = (const float*)d_in[12];
    const float* m1  = (const float*)d_in[13];
    const float* v1  = (const float*)d_in[14];
    const float* Wm2 = (const float*)d_in[15];
    const float* bm2 = (const float*)d_in[16];
    const float* g2  = (const float*)d_in[17];
    const float* b2  = (const float*)d_in[18];
    const float* m2  = (const float*)d_in[19];
    const float* v2  = (const float*)d_in[20];
    float* out = (float*)d_out;

    // L1: prep (128 blocks) + hist (3125 blocks)
    prep_hist_kernel<<<128 + (NE + 255) / 256, 256>>>(
        We1, be1, We2, be2, Wm1, bm1, g1, b1, m1, v1,
        Wm2, bm2, g2, b2, m2, v2, dst);
    // L2
    scan1_kernel<<<NB, 1024>>>();
    // L3: init (6250 blocks) + scatter (3125 blocks)
    scatter_init_kernel<<<INIT_BLOCKS + (NE + 255) / 256, 256>>>(
        src, dst, (const float4*)node, eps);
    // L4: accum (profiled launch)
    accum_kernel<<<ACC_BLOCKS, dim3(32, 4), ACC_SMEM>>>(node, efeat);

    float *pacc, *pt, *pW1, *pb1, *pW2, *pb2;
    cudaGetSymbolAddress((void**)&pacc, g_acc);
    cudaGetSymbolAddress((void**)&pt,   g_t);
    cudaGetSymbolAddress((void**)&pW1,  g_W1);
    cudaGetSymbolAddress((void**)&pb1,  g_b1);
    cudaGetSymbolAddress((void**)&pW2,  g_W2);
    cudaGetSymbolAddress((void**)&pb2,  g_b2);

    // L5 / L6 (L6 re-zeros count/cursor for the next call)
    gemm_kernel<<<dim3((NN + 127) / 128, 256 / 128), 256>>>(pacc, pW1, pb1, pt,
                                                            NN, 256, DD, 1, 0);
    gemm_kernel<<<dim3((NN + 127) / 128, DD / 128), 256>>>(pt, pW2, pb2, out,
                                                           NN, DD, 256, 0, 1);
}